// round 2
// baseline (speedup 1.0000x reference)
#include <cuda_runtime.h>
#include <math.h>

#define NN 200000
#define FF 256
#define CC 8
#define SC 16
#define EE 4000000
#define NSTEP 4
#define G3F 768
#define EPSF 1e-8f
#define MAXCAND 262144
#define NW (NN/4)

// output layout (float32, concatenated in reference-return order)
#define OUT_OUTPUTS 0        // 4*128*8 = 4096
#define OUT_SELECTS 4096     // 4*128   = 512
#define OUT_STEPS   4608     // 4*8     = 32
#define OUT_HX      4640     // 4*8*256 = 8192   (total 12832)

// ---------------- persistent device state (zero-init; self-cleaning across replays) ----
__device__ __align__(16) int g_counts[NN*CC];      // stays all-zero between launches
__device__ unsigned int  g_member_words[NW];       // class-membership bitmask, 1 byte/node
__device__ unsigned char g_entity[NN];
__device__ int           g_cand_pos[NN];           // 0 = none, else pos+1 (self-cleaned)
__device__ int           g_ncand;
__device__ int           g_cand_idx[MAXCAND];
__device__ unsigned int  g_cand_vmask[MAXCAND];
__device__ float         g_cand_sims[MAXCAND*CC];
__device__ float g_hx[CC*FF];
__device__ float g_hx_norm[CC*FF];
__device__ float g_inp[CC*FF];
__device__ float g_gi[CC*G3F];
__device__ float g_gh[CC*G3F];
__device__ int   g_last[CC*SC];
__device__ int   g_group[CC*SC];

// ---------------- init: masks, seeds, hx=0, steps output, pooling for step 0 ----------
__global__ void k_init(const int* __restrict__ seeds, const float* __restrict__ es,
                       float* __restrict__ out) {
    int g = blockIdx.x * blockDim.x + threadIdx.x;
    if (g < NN) g_entity[g] = (g < CC*SC) ? 1 : 0;
    if (g < NW) {
        unsigned w = 0;
        int base = g * 4;
        if (base < CC*SC) {
            #pragma unroll
            for (int b = 0; b < 4; b++) {
                int node = base + b;
                if (node < CC*SC) w |= ((unsigned)(1u << (node >> 4))) << (8 * b);
            }
        }
        g_member_words[g] = w;
    }
    if (g < CC*SC) g_last[g] = seeds[g];
    if (g < CC*FF) g_hx[g] = 0.f;
    if (g < NSTEP*CC) out[OUT_STEPS + g] = 16.0f;
    if (g == 0) g_ncand = 0;
    if (g < CC*FF) {   // heuristic pooling for step 0 directly from seeds
        int c = g >> 8, f = g & 255;
        float s = 0.f;
        for (int j = 0; j < SC; j++) s += es[(size_t)seeds[c*SC + j] * FF + f];
        g_inp[g] = s * (1.f / 16.f);
    }
}

// ---------------- GRU gate GEMM: gi = inp@W_ih^T + b_ih ; gh = hx@W_hh^T + b_hh -------
// 48 blocks: 0..23 cover W_ih rows, 24..47 cover W_hh rows; each W row read ONCE,
// reused for all 8 classes from shared memory.
__global__ void k_gates(const float* __restrict__ W_ih, const float* __restrict__ W_hh,
                        const float* __restrict__ b_ih, const float* __restrict__ b_hh) {
    __shared__ float sx[CC][FF];
    int half = blockIdx.x / 24;
    int k0   = (blockIdx.x % 24) * 32;
    const float* X = half ? g_hx  : g_inp;
    const float* W = half ? W_hh  : W_ih;
    const float* B = half ? b_hh  : b_ih;
    float* OUT     = half ? g_gh  : g_gi;
    for (int r = threadIdx.x; r < CC*FF; r += blockDim.x) sx[r >> 8][r & 255] = X[r];
    __syncthreads();
    int lane = threadIdx.x & 31, wid = threadIdx.x >> 5;
    for (int rr = wid; rr < 32; rr += 8) {
        int k = k0 + rr;
        float w[8];
        #pragma unroll
        for (int j = 0; j < 8; j++) w[j] = W[(size_t)k * FF + lane + 32*j];
        float bias = B[k];
        for (int c = 0; c < CC; c++) {
            float p = 0.f;
            #pragma unroll
            for (int j = 0; j < 8; j++) p += w[j] * sx[c][lane + 32*j];
            #pragma unroll
            for (int o = 16; o; o >>= 1) p += __shfl_down_sync(0xFFFFFFFFu, p, o);
            if (lane == 0) OUT[c*G3F + k] = p + bias;
        }
    }
}

// ---------------- GRU combine + row norm; writes output_hx --------------------------
__global__ void k_combine(int step, float* __restrict__ out) {
    int c = blockIdx.x, f = threadIdx.x;
    __shared__ float s_w[8];
    float ir = g_gi[c*G3F + f],       iz = g_gi[c*G3F + 256 + f], inn = g_gi[c*G3F + 512 + f];
    float hr = g_gh[c*G3F + f],       hz = g_gh[c*G3F + 256 + f], hn  = g_gh[c*G3F + 512 + f];
    float h  = g_hx[c*FF + f];
    float r  = 1.f / (1.f + expf(-(ir + hr)));
    float z  = 1.f / (1.f + expf(-(iz + hz)));
    float nn = tanhf(inn + r * hn);
    float hv = (1.f - z) * nn + z * h;
    g_hx[c*FF + f] = hv;
    out[OUT_HX + step*CC*FF + c*FF + f] = hv;
    float ss = hv * hv;
    #pragma unroll
    for (int o = 16; o; o >>= 1) ss += __shfl_down_sync(0xFFFFFFFFu, ss, o);
    int lane = f & 31, wid = f >> 5;
    if (lane == 0) s_w[wid] = ss;
    __syncthreads();
    if (f == 0) { float t = 0.f; for (int w = 0; w < 8; w++) t += s_w[w]; s_w[0] = t; }
    __syncthreads();
    float norm = sqrtf(s_w[0]);
    g_hx_norm[c*FF + f] = hv / (norm + EPSF);
}

// ---------------- edge counting: counts[src][c] += member(dst, c) -------------------
__global__ void k_edges(const int* __restrict__ esrc, const int4* __restrict__ edst4) {
    const unsigned char* mem = (const unsigned char*)g_member_words;
    int stride = gridDim.x * blockDim.x;
    for (int q = blockIdx.x * blockDim.x + threadIdx.x; q < EE/4; q += stride) {
        int4 d = edst4[q];
        unsigned m0 = mem[d.x], m1 = mem[d.y], m2 = mem[d.z], m3 = mem[d.w];
        if (m0 | m1 | m2 | m3) {
            int base = q * 4;
            int dd[4]      = {d.x, d.y, d.z, d.w};
            unsigned mk[4] = {m0, m1, m2, m3};
            (void)dd;
            #pragma unroll
            for (int j = 0; j < 4; j++) {
                unsigned m = mk[j];
                if (m) {
                    int s = esrc[base + j];
                    while (m) { int c = __ffs(m) - 1; m &= m - 1;
                                atomicAdd(&g_counts[(size_t)s*CC + c], 1); }
                }
            }
        }
    }
}

// ---------------- scan counts -> compact candidates, self-zero counts, compute sims --
__global__ void k_scan(const float* __restrict__ es, int mmv) {
    __shared__ int sh_n;
    __shared__ int sh_idx[256], sh_gp[256];
    __shared__ float s_part[CC][8];
    __shared__ float s_ss[8];
    if (threadIdx.x == 0) sh_n = 0;
    __syncthreads();
    int i = blockIdx.x * blockDim.x + threadIdx.x;
    if (i < NN) {
        int4 a = ((int4*)g_counts)[i*2];
        int4 b = ((int4*)g_counts)[i*2 + 1];
        if (a.x | a.y | a.z | a.w | b.x | b.y | b.z | b.w) {
            int4 zz = {0, 0, 0, 0};
            ((int4*)g_counts)[i*2] = zz;
            ((int4*)g_counts)[i*2 + 1] = zz;
            unsigned vm = 0;
            vm |= (unsigned)(a.x >= mmv);
            vm |= (unsigned)(a.y >= mmv) << 1;
            vm |= (unsigned)(a.z >= mmv) << 2;
            vm |= (unsigned)(a.w >= mmv) << 3;
            vm |= (unsigned)(b.x >= mmv) << 4;
            vm |= (unsigned)(b.y >= mmv) << 5;
            vm |= (unsigned)(b.z >= mmv) << 6;
            vm |= (unsigned)(b.w >= mmv) << 7;
            if (vm && !g_entity[i]) {
                int gp = atomicAdd(&g_ncand, 1);
                if (gp < MAXCAND) {
                    g_cand_idx[gp] = i; g_cand_vmask[gp] = vm; g_cand_pos[i] = gp + 1;
                    int lp = atomicAdd(&sh_n, 1);
                    if (lp < 256) { sh_idx[lp] = i; sh_gp[lp] = gp; }
                }
            }
        }
    }
    __syncthreads();
    int nloc = sh_n; if (nloc > 256) nloc = 256;
    int lane = threadIdx.x & 31, wid = threadIdx.x >> 5;
    for (int l = 0; l < nloc; l++) {
        int node = sh_idx[l], gp = sh_gp[l];
        float v = es[(size_t)node * FF + threadIdx.x];
        float ss = v * v;
        #pragma unroll
        for (int o = 16; o; o >>= 1) ss += __shfl_down_sync(0xFFFFFFFFu, ss, o);
        if (lane == 0) s_ss[wid] = ss;
        __syncthreads();
        if (threadIdx.x == 0) { float t = 0.f; for (int w = 0; w < 8; w++) t += s_ss[w]; s_ss[0] = t; }
        __syncthreads();
        float vn = v / (sqrtf(s_ss[0]) + EPSF);
        for (int c = 0; c < CC; c++) {
            float p = vn * g_hx_norm[c*FF + threadIdx.x];
            #pragma unroll
            for (int o = 16; o; o >>= 1) p += __shfl_down_sync(0xFFFFFFFFu, p, o);
            if (lane == 0) s_part[c][wid] = p;
        }
        __syncthreads();
        if (threadIdx.x < CC) {
            float t = 0.f;
            for (int w = 0; w < 8; w++) t += s_part[threadIdx.x][w];
            g_cand_sims[gp*CC + threadIdx.x] = t * 0.5f + 0.5f;
        }
        __syncthreads();
    }
}

// ---------------- per-class top-16 with jax.lax.top_k tie semantics -----------------
// valid candidates by (prob desc, idx asc); remaining slots filled with the
// smallest-index nodes that are NOT valid for this class (their score is -1).
__global__ void k_select(int step, float* __restrict__ out) {
    int c = blockIdx.x, t = threadIdx.x;
    __shared__ unsigned long long s_red[8];
    __shared__ unsigned long long s_best;
    __shared__ int s_group[SC];
    __shared__ unsigned char s_inval[256];
    {
        int p = g_cand_pos[t];
        s_inval[t] = !(p && ((g_cand_vmask[p-1] >> c) & 1));
    }
    int n = g_ncand; if (n > MAXCAND) n = MAXCAND;
    __syncthreads();
    unsigned long long prev = 0xFFFFFFFFFFFFFFFFull;
    int nsel = 0;
    for (int round = 0; round < SC; round++) {
        unsigned long long best = 0;
        for (int i = t; i < n; i += 256) {
            if ((g_cand_vmask[i] >> c) & 1) {
                float prob = g_cand_sims[i*CC + c];
                unsigned u = __float_as_uint(prob);
                u = (u >> 31) ? ~u : (u | 0x80000000u);   // order-preserving float->uint
                unsigned long long key =
                    ((unsigned long long)u << 32) | (unsigned)(~(unsigned)g_cand_idx[i]);
                if (key < prev && key > best) best = key;
            }
        }
        int lane = t & 31, wid = t >> 5;
        #pragma unroll
        for (int o = 16; o; o >>= 1) {
            unsigned long long v = __shfl_down_sync(0xFFFFFFFFu, best, o);
            if (v > best) best = v;
        }
        if (lane == 0) s_red[wid] = best;
        __syncthreads();
        if (t == 0) {
            unsigned long long b = 0;
            for (int w = 0; w < 8; w++) if (s_red[w] > b) b = s_red[w];
            s_best = b;
        }
        __syncthreads();
        unsigned long long ball = s_best;
        if (ball == 0) break;                      // no more valid candidates
        if (t == 0) s_group[round] = (int)(~(unsigned)ball);
        prev = ball; nsel = round + 1;
        __syncthreads();
    }
    if (t == 0) {
        int j = 0;
        for (int slot = nsel; slot < SC; slot++) {
            while (j < NN) {
                bool inval;
                if (j < 256) inval = s_inval[j];
                else { int p = g_cand_pos[j]; inval = !(p && ((g_cand_vmask[p-1] >> c) & 1)); }
                if (inval) break;
                j++;
            }
            s_group[slot] = j; j++;
        }
    }
    __syncthreads();
    if (t < SC) {
        int idx = s_group[t];
        g_group[c*SC + t] = idx;
        out[OUT_SELECTS + step*(CC*SC) + c*SC + t] = (float)idx;
    }
}

// ---------------- finalize: probs output, mask updates, next pooling, cleanup -------
__global__ void k_final(int step, const float* __restrict__ es, float* __restrict__ out) {
    int t = threadIdx.x;
    // outputs = probs[flat]  (probs = cate_pools ? sims : 0)
    for (int q = t; q < CC*SC*CC; q += 256) {
        int flat = q >> 3, c2 = q & 7;
        int node = g_group[flat];
        int p = g_cand_pos[node];
        float val = p ? g_cand_sims[(p-1)*CC + c2] : 0.f;
        out[OUT_OUTPUTS + step*(CC*SC*CC) + flat*CC + c2] = val;
    }
    __syncthreads();
    if (t < CC*SC) {
        int node = g_group[t];
        g_entity[node] = 1;
        unsigned bit = 1u << (t / SC);
        atomicOr(&g_member_words[node >> 2], bit << ((node & 3) * 8));
        g_last[t] = node;
    }
    __syncthreads();
    // heuristic pooling for NEXT step
    for (int q = t; q < CC*FF; q += 256) {
        int c = q >> 8, f = q & 255;
        float s = 0.f;
        for (int j = 0; j < SC; j++) s += es[(size_t)g_last[c*SC + j] * FF + f];
        g_inp[q] = s * (1.f / 16.f);
    }
    __syncthreads();
    // cleanup: cand_pos entries and ncand -> replay-deterministic state
    int n = g_ncand; if (n > MAXCAND) n = MAXCAND;
    for (int i = t; i < n; i += 256) g_cand_pos[g_cand_idx[i]] = 0;
    __syncthreads();
    if (t == 0) g_ncand = 0;
}

// ---------------- launch -----------------------------------------------------------
extern "C" void kernel_launch(void* const* d_in, const int* in_sizes, int n_in,
                              void* d_out, int out_size) {
    const int*   seeds = (const int*)d_in[0];
    const int*   esrc  = (const int*)d_in[1];
    const int*   edst  = (const int*)d_in[2];
    const float* es    = (const float*)d_in[3];
    const float* W_ih  = (const float*)d_in[4];
    const float* W_hh  = (const float*)d_in[5];
    const float* b_ih  = (const float*)d_in[6];
    const float* b_hh  = (const float*)d_in[7];
    float* out = (float*)d_out;
    (void)in_sizes; (void)n_in; (void)out_size;

    k_init<<<784, 256>>>(seeds, es, out);
    const int mms[4] = {3, 2, 2, 2};   // mm = max(2, MIN_MATCH - rnn_i)
    for (int s = 0; s < 4; s++) {
        k_gates  <<<48,   256>>>(W_ih, W_hh, b_ih, b_hh);
        k_combine<<<8,    256>>>(s, out);
        k_edges  <<<1184, 256>>>(esrc, (const int4*)edst);
        k_scan   <<<784,  256>>>(es, mms[s]);
        k_select <<<8,    256>>>(s, out);
        k_final  <<<1,    256>>>(s, es, out);
    }
}